// round 10
// baseline (speedup 1.0000x reference)
#include <cuda_runtime.h>
#include <math.h>

#define SLEN   2048
#define HEADS  32
#define DHEAD  128
#define TQ     64
#define TK     64
#define NT     256

// ---------------- shared memory layout ----------------
// Qs/Ks/Vs: [64 rows][32 float4] with XOR swizzle  phys_d4 = d4 ^ (row & 7)
// Ws:       [64 cols][68 floats] (pitch 68 keeps float4 reads aligned)
struct __align__(16) Smem {
    float4 Qs[TQ * 32];
    float4 Ks[TK * 32];
    float4 Vs[TK * 32];
    float  Ws[TK * 68];
};

// f32 exp(x) for |x| <= 0.4 (~0.5 ulp), used in pass 1 only (feeds fp64 sum).
__device__ __forceinline__ float expP(float x)
{
    float p = 1.0f / 5040.0f;
    p = fmaf(p, x, 1.0f / 720.0f);
    p = fmaf(p, x, 1.0f / 120.0f);
    p = fmaf(p, x, 1.0f / 24.0f);
    p = fmaf(p, x, 1.0f / 6.0f);
    p = fmaf(p, x, 0.5f);
    p = fmaf(p, x, 1.0f);
    return fmaf(p, x, 1.0f);
}

// Correctly-rounded f32 exp for t in [-0.4, 0]: degree-10 Taylor in double
// (truncation < 1e-14 rel), single rounding to f32. Matches a correctly
// rounded libm expf bit-for-bit. Pass 2 only.
__device__ __forceinline__ float expCR(float t)
{
    const double x = (double)t;
    double p = 1.0 / 3628800.0;
    p = fma(p, x, 1.0 / 362880.0);
    p = fma(p, x, 1.0 / 40320.0);
    p = fma(p, x, 1.0 / 5040.0);
    p = fma(p, x, 1.0 / 720.0);
    p = fma(p, x, 1.0 / 120.0);
    p = fma(p, x, 1.0 / 24.0);
    p = fma(p, x, 1.0 / 6.0);
    p = fma(p, x, 0.5);
    p = fma(p, x, 1.0);
    p = fma(p, x, 1.0);
    return (float)p;
}

// 64x64x128 fp32 GEMM: s[i][u] = dot(Q row 4*ty+i, K row tx+16*u)
// Sequential ascending-d single-accumulator FMA chain == Eigen gebp order,
// shared (inlined) by pass 1 and pass 2 so both produce bit-identical scores.
__device__ __forceinline__ void gemm_qk(const Smem& sm, int tx, int ty, float s[4][4])
{
    #pragma unroll
    for (int i = 0; i < 4; ++i)
        #pragma unroll
        for (int u = 0; u < 4; ++u)
            s[i][u] = 0.0f;

    #pragma unroll 8
    for (int d4 = 0; d4 < 32; ++d4) {
        float4 q4[4], k4[4];
        #pragma unroll
        for (int i = 0; i < 4; ++i) {
            const int r = 4 * ty + i;
            q4[i] = sm.Qs[r * 32 + (d4 ^ (r & 7))];
        }
        #pragma unroll
        for (int u = 0; u < 4; ++u) {
            const int c = tx + 16 * u;
            k4[u] = sm.Ks[c * 32 + (d4 ^ (c & 7))];
        }
        #pragma unroll
        for (int i = 0; i < 4; ++i)
            #pragma unroll
            for (int u = 0; u < 4; ++u) {
                s[i][u] = fmaf(q4[i].x, k4[u].x, s[i][u]);
                s[i][u] = fmaf(q4[i].y, k4[u].y, s[i][u]);
                s[i][u] = fmaf(q4[i].z, k4[u].z, s[i][u]);
                s[i][u] = fmaf(q4[i].w, k4[u].w, s[i][u]);
            }
    }
}

// v = s*norm + am (ref op order), dead[..] = causal-masked.
// Deterministic, used IDENTICALLY in both passes.
__device__ __forceinline__ void scale_mask(float s[4][4], float v[4][4], int dead[4][4],
                                           const float* __restrict__ am,
                                           int kb, int tx, int ty, int q0, bool diag,
                                           float norm)
{
    float amv[4];
    #pragma unroll
    for (int u = 0; u < 4; ++u) amv[u] = __ldg(&am[kb + tx + 16 * u]);

    #pragma unroll
    for (int i = 0; i < 4; ++i) {
        const int qr = q0 + 4 * ty + i;
        #pragma unroll
        for (int u = 0; u < 4; ++u) {
            const int kc = kb + tx + 16 * u;
            v[i][u] = __fadd_rn(__fmul_rn(s[i][u], norm), amv[u]);
            dead[i][u] = diag && (kc > qr);
        }
    }
}

__global__ void __launch_bounds__(NT)
attn_kernel(const float* __restrict__ Q, const float* __restrict__ K,
            const float* __restrict__ V, const float* __restrict__ AM,
            float* __restrict__ O)
{
    extern __shared__ float4 smem_raw[];
    Smem& sm = *reinterpret_cast<Smem*>(smem_raw);

    const int tid = threadIdx.x;
    const int tx  = tid & 15;        // 16 column-group lanes
    const int ty  = tid >> 4;        // 16 row groups of 4
    const int qt  = (int)gridDim.x - 1 - (int)blockIdx.x;  // heavy tiles first
    const int bh  = (int)blockIdx.y;
    const int b   = bh >> 5;
    const int h   = bh & 31;
    const int q0  = qt * TQ;

    // norm exactly as numpy computes it, rounding at every f32 step:
    //   a = f32(sqrt(128.)) ; b = f32(1/a) ; norm = f32(f32(b*0.1f)*0.1f)
    const float sq128 = (float)11.313708498984761;   // f32(np.sqrt(128))
    const float norm  = __fmul_rn(__fmul_rn(__fdiv_rn(1.0f, sq128), 0.1f), 0.1f);
    const float c1    = (float)((1.0 / 255.0) * (1.0 / 10.0)); // f32((1/255)*(1/10))

    const size_t base = (size_t)bh * SLEN * DHEAD;
    const float* am   = AM + (size_t)b * SLEN;
    const float4* gq  = reinterpret_cast<const float4*>(Q + base) + (size_t)q0 * (DHEAD / 4);
    const float4* gk0 = reinterpret_cast<const float4*>(K + base);
    const float4* gv0 = reinterpret_cast<const float4*>(V + base);

    // ---- load Q tile (coalesced, XOR-swizzled store) ----
    #pragma unroll
    for (int j = 0; j < 8; ++j) {
        const int i = tid + NT * j;
        const int r = i >> 5, d4 = i & 31;
        sm.Qs[r * 32 + (d4 ^ (r & 7))] = gq[i];
    }

    // Row stats: m = exact f32 max of masked scores; L = fp64 sum of exp(v)
    // (unshifted; logits tiny so no overflow; no online rescaling error).
    double L[4];
    float  m[4];
    #pragma unroll
    for (int i = 0; i < 4; ++i) { L[i] = 0.0; m[i] = -3.402823466e38f; }

    // ================= pass 1: row max m and unshifted denom L =================
    {
        float4 pk[8];
        #pragma unroll
        for (int j = 0; j < 8; ++j) pk[j] = gk0[tid + NT * j];
        #pragma unroll
        for (int j = 0; j < 8; ++j) {
            const int i = tid + NT * j;
            const int r = i >> 5, d4 = i & 31;
            sm.Ks[r * 32 + (d4 ^ (r & 7))] = pk[j];
        }
        __syncthreads();

        for (int kt = 0; kt <= qt; ++kt) {
            // prefetch next K tile into registers (hides LDG latency behind GEMM)
            if (kt < qt) {
                const float4* gk = gk0 + (size_t)(kt + 1) * TK * (DHEAD / 4);
                #pragma unroll
                for (int j = 0; j < 8; ++j) pk[j] = gk[tid + NT * j];
            }

            float s[4][4];
            gemm_qk(sm, tx, ty, s);
            __syncthreads();                 // everyone done reading Ks

            if (kt < qt) {                   // stage next tile
                #pragma unroll
                for (int j = 0; j < 8; ++j) {
                    const int i = tid + NT * j;
                    const int r = i >> 5, d4 = i & 31;
                    sm.Ks[r * 32 + (d4 ^ (r & 7))] = pk[j];
                }
            }

            float v[4][4]; int dead[4][4];
            scale_mask(s, v, dead, am, kt * TK, tx, ty, q0, kt == qt, norm);

            #pragma unroll
            for (int i = 0; i < 4; ++i) {
                float e0 = dead[i][0] ? 0.0f : expP(v[i][0]);
                float e1 = dead[i][1] ? 0.0f : expP(v[i][1]);
                float e2 = dead[i][2] ? 0.0f : expP(v[i][2]);
                float e3 = dead[i][3] ? 0.0f : expP(v[i][3]);

                // row max of v (exact, order independent); dead -> -FLT_MAX
                float t0 = dead[i][0] ? -3.402823466e38f : v[i][0];
                float t1 = dead[i][1] ? -3.402823466e38f : v[i][1];
                float t2 = dead[i][2] ? -3.402823466e38f : v[i][2];
                float t3 = dead[i][3] ? -3.402823466e38f : v[i][3];
                float t = fmaxf(fmaxf(t0, t1), fmaxf(t2, t3));
                #pragma unroll
                for (int msk = 1; msk < 16; msk <<= 1)
                    t = fmaxf(t, __shfl_xor_sync(0xffffffffu, t, msk));
                m[i] = fmaxf(m[i], t);

                // fp64 row-sum of exp(v)
                double rs = ((double)e0 + (double)e1) + ((double)e2 + (double)e3);
                #pragma unroll
                for (int msk = 1; msk < 16; msk <<= 1)
                    rs += __shfl_xor_sync(0xffffffffu, rs, msk);
                L[i] += rs;
            }
            __syncthreads();
        }
    }

    // ---- l in f32 (the value the reference divides by): l = L * exp(-m) ----
    // Near-exact (error ~1e-9 rel, far below the reference's own sum error).
    float lf[4];
    int needp = 0;
    #pragma unroll
    for (int i = 0; i < 4; ++i) {
        lf[i] = (float)(L[i] * exp(-(double)m[i]));
        // skip test with EXACTLY the pass-2 weight arithmetic at e = 1
        // (argmax element always has e = expCR(0) = 1): monotone in e.
        const float zmax = __fmul_rn(__fdiv_rn(1.0f, lf[i]), 255.0f);
        if (rintf(zmax) >= 1.0f) needp = 1;
    }
    const int need = __syncthreads_or(needp);

    if (!need) {
        // whole tile quantizes to zero — write zeros (out is poisoned)
        const float4 z = make_float4(0.f, 0.f, 0.f, 0.f);
        #pragma unroll
        for (int i = 0; i < 4; ++i) {
            const int row = q0 + 4 * ty + i;
            float4* p = reinterpret_cast<float4*>(
                O + ((size_t)b * SLEN + row) * (HEADS * DHEAD) + h * DHEAD + 8 * tx);
            p[0] = z; p[1] = z;
        }
        return;
    }

    // ================= pass 2: quantized weights + W @ V =================
    // fp32 accumulators updated by fmaf in STRICTLY ascending k order:
    // emulates Eigen's sequential-k gebp accumulation (what the reference's
    // fp32 einsum does). Zero weights add exactly 0 -> order preserved.
    float acc[4][8];
    #pragma unroll
    for (int i = 0; i < 4; ++i)
        #pragma unroll
        for (int jj = 0; jj < 8; ++jj) acc[i][jj] = 0.0f;

    for (int kt = 0; kt <= qt; ++kt) {
        __syncthreads();   // previous iteration's Vs/Ws readers done
        {
            const float4* gk = gk0 + (size_t)kt * TK * (DHEAD / 4);
            const float4* gv = gv0 + (size_t)kt * TK * (DHEAD / 4);
            #pragma unroll
            for (int j = 0; j < 8; ++j) {
                const int i = tid + NT * j;
                const int r = i >> 5, d4 = i & 31;
                const int idx = r * 32 + (d4 ^ (r & 7));
                sm.Ks[idx] = gk[i];
                sm.Vs[idx] = gv[i];
            }
        }
        __syncthreads();

        float s[4][4];
        gemm_qk(sm, tx, ty, s);                                 // identical to pass 1
        float v[4][4]; int dead[4][4];
        scale_mask(s, v, dead, am, kt * TK, tx, ty, q0, kt == qt, norm);

        // e = exp(f32(v - m)) correctly rounded (== ref softmax numerator);
        // w = rint(f32(f32(e / l) * 255)) clip 255 — ref's exact op chain.
        #pragma unroll
        for (int u = 0; u < 4; ++u) {
            const int c = tx + 16 * u;
            #pragma unroll
            for (int i = 0; i < 4; ++i) {
                float w;
                if (dead[i][u]) {
                    w = 0.0f;
                } else {
                    const float t = __fadd_rn(v[i][u], -m[i]);  // f32 (s - max)
                    const float e = expCR(t);                   // = 1.0f at argmax
                    const float z = __fmul_rn(__fdiv_rn(e, lf[i]), 255.0f);
                    w = fminf(rintf(z), 255.0f);
                }
                sm.Ws[c * 68 + 4 * ty + i] = w;
            }
        }
        __syncthreads();

        // acc[r][d] += W[r][c] * V[c][d], c ascending 0..63 (global k ascending)
        #pragma unroll 8
        for (int c = 0; c < 64; ++c) {
            const float4 w4 = *reinterpret_cast<const float4*>(&sm.Ws[c * 68 + 4 * ty]);
            const float4 v0 = sm.Vs[c * 32 + ((2 * tx)     ^ (c & 7))];
            const float4 v1 = sm.Vs[c * 32 + ((2 * tx + 1) ^ (c & 7))];
            const float wv[4] = { w4.x, w4.y, w4.z, w4.w };
            #pragma unroll
            for (int i = 0; i < 4; ++i) {
                acc[i][0] = fmaf(wv[i], v0.x, acc[i][0]);
                acc[i][1] = fmaf(wv[i], v0.y, acc[i][1]);
                acc[i][2] = fmaf(wv[i], v0.z, acc[i][2]);
                acc[i][3] = fmaf(wv[i], v0.w, acc[i][3]);
                acc[i][4] = fmaf(wv[i], v1.x, acc[i][4]);
                acc[i][5] = fmaf(wv[i], v1.y, acc[i][5]);
                acc[i][6] = fmaf(wv[i], v1.z, acc[i][6]);
                acc[i][7] = fmaf(wv[i], v1.w, acc[i][7]);
            }
        }
    }

    // ---- epilogue: exact ref op order on the (emulated) f32 einsum result ----
    #pragma unroll
    for (int i = 0; i < 4; ++i) {
        float o[8];
        #pragma unroll
        for (int jj = 0; jj < 8; ++jj) {
            float y = __fmul_rn(acc[i][jj], c1);   // out * f32(1/2550)
            y = __fmul_rn(y, 127.0f);              // * REQUANT
            y = rintf(y);                          // round half-to-even
            o[jj] = fminf(fmaxf(y, -128.0f), 127.0f);
        }
        const int row = q0 + 4 * ty + i;
        float4* p = reinterpret_cast<float4*>(
            O + ((size_t)b * SLEN + row) * (HEADS * DHEAD) + h * DHEAD + 8 * tx);
        p[0] = make_float4(o[0], o[1], o[2], o[3]);
        p[1] = make_float4(o[4], o[5], o[6], o[7]);
    }
}

extern "C" void kernel_launch(void* const* d_in, const int* in_sizes, int n_in,
                              void* d_out, int out_size)
{
    (void)in_sizes; (void)n_in; (void)out_size;
    const float* q  = (const float*)d_in[0];
    const float* k  = (const float*)d_in[1];
    const float* v  = (const float*)d_in[2];
    const float* am = (const float*)d_in[3];
    float* out = (float*)d_out;

    const int smem = (int)sizeof(Smem);   // 115712 B
    cudaFuncSetAttribute(attn_kernel, cudaFuncAttributeMaxDynamicSharedMemorySize, smem);

    dim3 grid(SLEN / TQ, 2 * HEADS);      // (32 q-tiles, 64 batch*head)
    attn_kernel<<<grid, NT, smem>>>(q, k, v, am, out);
}